// round 4
// baseline (speedup 1.0000x reference)
#include <cuda_runtime.h>
#include <cuda_bf16.h>

// Problem constants
#define B   2
#define C   256
#define S   4096      // H*W = 64*64
#define NH  4
#define HD  64        // head dim
#define NG  32
#define GC  8         // channels per group

// Scratch (allocation-free per harness rules)
__device__ float g_hn[B * C * S];          // groupnorm output, [b][c][s]
__device__ float g_q [B * NH * HD * S];    // [b][n][d][s], pre-scaled by 1/8
__device__ float g_k [B * NH * HD * S];
__device__ float g_v [B * NH * HD * S];
__device__ float g_ao[B * C * S];          // attention out, [b][c][s] with c = d*4+n

// ---------------------------------------------------------------------------
// GroupNorm: one CTA per (b, group). 8 ch x 4096 = 32768 elems.
// ---------------------------------------------------------------------------
__global__ __launch_bounds__(256) void gn_kernel(
    const float* __restrict__ x,
    const float* __restrict__ gamma,
    const float* __restrict__ beta)
{
    int g = blockIdx.x & (NG - 1);
    int b = blockIdx.x >> 5;
    const float4* xp = (const float4*)(x + (b * C + g * GC) * S);
    float4*       hp = (float4*)(g_hn + (b * C + g * GC) * S);

    float sum = 0.f, sq = 0.f;
    // 8192 float4 per group, 256 threads -> 32 each
    for (int i = threadIdx.x; i < 8192; i += 256) {
        float4 v = xp[i];
        sum += v.x + v.y + v.z + v.w;
        sq  += v.x * v.x + v.y * v.y + v.z * v.z + v.w * v.w;
    }
    // warp reduce
    for (int o = 16; o > 0; o >>= 1) {
        sum += __shfl_xor_sync(0xffffffffu, sum, o);
        sq  += __shfl_xor_sync(0xffffffffu, sq,  o);
    }
    __shared__ float ssum[8], ssq[8], sstat[2];
    int wid = threadIdx.x >> 5, lid = threadIdx.x & 31;
    if (lid == 0) { ssum[wid] = sum; ssq[wid] = sq; }
    __syncthreads();
    if (threadIdx.x == 0) {
        float ts = 0.f, tq = 0.f;
        #pragma unroll
        for (int i = 0; i < 8; i++) { ts += ssum[i]; tq += ssq[i]; }
        float mu  = ts * (1.f / 32768.f);
        float var = tq * (1.f / 32768.f) - mu * mu;
        sstat[0] = mu;
        sstat[1] = rsqrtf(var + 1e-5f);
    }
    __syncthreads();
    float mu = sstat[0], rstd = sstat[1];

    for (int i = threadIdx.x; i < 8192; i += 256) {
        float4 v = xp[i];
        int ch = g * GC + (i >> 10);     // 1024 float4 per channel
        float gm = gamma[ch] * rstd;
        float bt = beta[ch] - mu * gm;
        float4 o;
        o.x = v.x * gm + bt; o.y = v.y * gm + bt;
        o.z = v.z * gm + bt; o.w = v.w * gm + bt;
        hp[i] = o;
    }
}

// ---------------------------------------------------------------------------
// Shared GEMM body: 64x64 tile, K=256, 128 threads, 8x4 microtile
// ---------------------------------------------------------------------------
struct GemmAcc { float a[8][4]; };

__device__ __forceinline__ void gemm_64x64_k256(
    const float* __restrict__ W,    // [64 rows starting m0][256], row stride 256
    const float* __restrict__ in,   // [256][4096], cols n0..n0+63
    int m0, int n0, GemmAcc& acc)
{
    __shared__ float As[16][64];
    __shared__ float Bs[16][64];
    int tid = threadIdx.x;
    int tm = (tid >> 4) * 8, tn = (tid & 15) * 4;

    #pragma unroll
    for (int r = 0; r < 8; r++)
        #pragma unroll
        for (int c = 0; c < 4; c++) acc.a[r][c] = 0.f;

    for (int k0 = 0; k0 < 256; k0 += 16) {
        #pragma unroll
        for (int i = 0; i < 2; i++) {
            int f = tid + i * 128;          // 0..255
            int r = f >> 2;                 // 0..63
            int kc = (f & 3) * 4;           // 0,4,8,12
            float4 a = *(const float4*)&W[(m0 + r) * C + k0 + kc];
            As[kc + 0][r] = a.x; As[kc + 1][r] = a.y;
            As[kc + 2][r] = a.z; As[kc + 3][r] = a.w;
        }
        #pragma unroll
        for (int i = 0; i < 2; i++) {
            int f = tid + i * 128;
            int kr = f >> 4;                // 0..15
            int nc = (f & 15) * 4;
            *(float4*)&Bs[kr][nc] = *(const float4*)&in[(k0 + kr) * S + n0 + nc];
        }
        __syncthreads();
        #pragma unroll
        for (int k = 0; k < 16; k++) {
            float4 a0 = *(const float4*)&As[k][tm];
            float4 a1 = *(const float4*)&As[k][tm + 4];
            float4 bb = *(const float4*)&Bs[k][tn];
            float ar[8] = {a0.x, a0.y, a0.z, a0.w, a1.x, a1.y, a1.z, a1.w};
            float br[4] = {bb.x, bb.y, bb.z, bb.w};
            #pragma unroll
            for (int r = 0; r < 8; r++)
                #pragma unroll
                for (int c = 0; c < 4; c++)
                    acc.a[r][c] += ar[r] * br[c];
        }
        __syncthreads();
    }
}

// QKV: grid (64, 4, 6) : z = b*3 + which. Writes head-separated layout.
__global__ __launch_bounds__(128) void qkv_gemm(
    const float* __restrict__ wq, const float* __restrict__ bq,
    const float* __restrict__ wk, const float* __restrict__ bk,
    const float* __restrict__ wv, const float* __restrict__ bv)
{
    int n0 = blockIdx.x * 64;
    int m0 = blockIdx.y * 64;
    int z = blockIdx.z;
    int b = z / 3, t = z - b * 3;
    const float* W    = (t == 0) ? wq : (t == 1) ? wk : wv;
    const float* bias = (t == 0) ? bq : (t == 1) ? bk : bv;
    float* outb       = (t == 0) ? g_q : (t == 1) ? g_k : g_v;
    const float* in   = g_hn + b * C * S;
    float scale = (t == 0) ? 0.125f : 1.0f;   // q pre-scaled by d^-0.5

    GemmAcc acc;
    gemm_64x64_k256(W, in, m0, n0, acc);

    int tid = threadIdx.x;
    int tm = (tid >> 4) * 8, tn = (tid & 15) * 4;
    #pragma unroll
    for (int r = 0; r < 8; r++) {
        int o = m0 + tm + r;                 // out channel
        float bb = bias[o];
        int head = o & 3, ci = o >> 2;       // ch = ci*4 + head (head_dim leading reshape)
        float4 v;
        v.x = (acc.a[r][0] + bb) * scale;
        v.y = (acc.a[r][1] + bb) * scale;
        v.z = (acc.a[r][2] + bb) * scale;
        v.w = (acc.a[r][3] + bb) * scale;
        *(float4*)&outb[((b * NH + head) * HD + ci) * S + n0 + tn] = v;
    }
}

// Proj + residual: grid (64, 4, 2)
__global__ __launch_bounds__(128) void proj_gemm(
    const float* __restrict__ wp, const float* __restrict__ bp,
    const float* __restrict__ x, float* __restrict__ out)
{
    int n0 = blockIdx.x * 64;
    int m0 = blockIdx.y * 64;
    int b = blockIdx.z;
    const float* in = g_ao + b * C * S;

    GemmAcc acc;
    gemm_64x64_k256(wp, in, m0, n0, acc);

    int tid = threadIdx.x;
    int tm = (tid >> 4) * 8, tn = (tid & 15) * 4;
    #pragma unroll
    for (int r = 0; r < 8; r++) {
        int o = m0 + tm + r;
        float bb = bp[o];
        const float4 xr = *(const float4*)&x[(b * C + o) * S + n0 + tn];
        float4 v;
        v.x = acc.a[r][0] + bb + xr.x;
        v.y = acc.a[r][1] + bb + xr.y;
        v.z = acc.a[r][2] + bb + xr.z;
        v.w = acc.a[r][3] + bb + xr.w;
        *(float4*)&out[(b * C + o) * S + n0 + tn] = v;
    }
}

// ---------------------------------------------------------------------------
// Flash attention: 1 query per thread, 128 queries per CTA.
// K/V tiles of 64 keys in smem [d][j] layout -> all reads are warp-broadcast.
// grid (32, 4, 2)
// ---------------------------------------------------------------------------
#define QK4(S0, KV) { s[S0]+=qd*KV.x; s[S0+1]+=qd*KV.y; s[S0+2]+=qd*KV.z; s[S0+3]+=qd*KV.w; }
#define PV4(S0, KV) { a += s[S0]*KV.x; a += s[S0+1]*KV.y; a += s[S0+2]*KV.z; a += s[S0+3]*KV.w; }

__global__ __launch_bounds__(128) void attn_kernel()
{
    int n = blockIdx.y, b = blockIdx.z;
    int qi = blockIdx.x * 128 + threadIdx.x;
    const float* Q = g_q + (b * NH + n) * HD * S;
    const float* K = g_k + (b * NH + n) * HD * S;
    const float* V = g_v + (b * NH + n) * HD * S;

    __shared__ float Ks[HD][64];
    __shared__ float Vs[HD][64];

    float qv[HD];
    #pragma unroll
    for (int d = 0; d < HD; d++) qv[d] = Q[d * S + qi];

    float acc[HD];
    #pragma unroll
    for (int d = 0; d < HD; d++) acc[d] = 0.f;
    float m = -1e30f, l = 0.f;

    #pragma unroll 1
    for (int k0 = 0; k0 < S; k0 += 64) {
        #pragma unroll
        for (int i = 0; i < 8; i++) {
            int f = threadIdx.x + i * 128;   // 0..1023
            int d = f >> 4, j4 = (f & 15) * 4;
            *(float4*)&Ks[d][j4] = *(const float4*)&K[d * S + k0 + j4];
            *(float4*)&Vs[d][j4] = *(const float4*)&V[d * S + k0 + j4];
        }
        __syncthreads();

        #pragma unroll 1
        for (int sub = 0; sub < 4; sub++) {
            int j0 = sub * 16;
            float s[16];
            #pragma unroll
            for (int j = 0; j < 16; j++) s[j] = 0.f;

            #pragma unroll
            for (int d = 0; d < HD; d++) {
                float qd = qv[d];
                float4 k0v = *(const float4*)&Ks[d][j0];
                float4 k1v = *(const float4*)&Ks[d][j0 + 4];
                float4 k2v = *(const float4*)&Ks[d][j0 + 8];
                float4 k3v = *(const float4*)&Ks[d][j0 + 12];
                QK4(0,  k0v) QK4(4,  k1v) QK4(8,  k2v) QK4(12, k3v)
            }
            // online softmax over 16 keys
            float mt = s[0];
            #pragma unroll
            for (int j = 1; j < 16; j++) mt = fmaxf(mt, s[j]);
            float mnew = fmaxf(m, mt);
            float corr = __expf(m - mnew);
            float psum = 0.f;
            #pragma unroll
            for (int j = 0; j < 16; j++) { s[j] = __expf(s[j] - mnew); psum += s[j]; }
            l = l * corr + psum;
            m = mnew;

            #pragma unroll
            for (int d = 0; d < HD; d++) {
                float4 v0 = *(const float4*)&Vs[d][j0];
                float4 v1 = *(const float4*)&Vs[d][j0 + 4];
                float4 v2 = *(const float4*)&Vs[d][j0 + 8];
                float4 v3 = *(const float4*)&Vs[d][j0 + 12];
                float a = acc[d] * corr;
                PV4(0,  v0) PV4(4,  v1) PV4(8,  v2) PV4(12, v3)
                acc[d] = a;
            }
        }
        __syncthreads();
    }

    float inv = 1.f / l;
    #pragma unroll
    for (int d = 0; d < HD; d++)
        g_ao[(b * C + d * NH + n) * S + qi] = acc[d] * inv;
}

// ---------------------------------------------------------------------------
extern "C" void kernel_launch(void* const* d_in, const int* in_sizes, int n_in,
                              void* d_out, int out_size)
{
    const float* x     = (const float*)d_in[0];
    const float* gamma = (const float*)d_in[1];
    const float* beta  = (const float*)d_in[2];
    const float* wq    = (const float*)d_in[3];
    const float* bq    = (const float*)d_in[4];
    const float* wk    = (const float*)d_in[5];
    const float* bk    = (const float*)d_in[6];
    const float* wv    = (const float*)d_in[7];
    const float* bv    = (const float*)d_in[8];
    const float* wp    = (const float*)d_in[9];
    const float* bp    = (const float*)d_in[10];
    float* out = (float*)d_out;

    gn_kernel<<<B * NG, 256>>>(x, gamma, beta);
    qkv_gemm<<<dim3(S / 64, C / 64, B * 3), 128>>>(wq, bq, wk, bk, wv, bv);
    attn_kernel<<<dim3(S / 128, NH, B), 128>>>();
    proj_gemm<<<dim3(S / 64, C / 64, B), 128>>>(wp, bp, x, out);
}

// round 7
// speedup vs baseline: 1.6081x; 1.6081x over previous
#include <cuda_runtime.h>
#include <cuda_bf16.h>

// Problem constants
#define B   2
#define C   256
#define S   4096      // H*W = 64*64
#define NH  4
#define HD  64        // head dim
#define NG  32
#define GC  8         // channels per group

typedef unsigned long long ull;

// ---- packed f32x2 helpers (sm_100+ PTX) -----------------------------------
__device__ __forceinline__ ull pk2(float lo, float hi) {
    ull r; asm("mov.b64 %0,{%1,%2};" : "=l"(r) : "f"(lo), "f"(hi)); return r;
}
__device__ __forceinline__ void upk2(ull v, float& lo, float& hi) {
    asm("mov.b64 {%0,%1},%2;" : "=f"(lo), "=f"(hi) : "l"(v));
}
__device__ __forceinline__ ull fma2(ull a, ull b, ull c) {
    ull d; asm("fma.rn.f32x2 %0,%1,%2,%3;" : "=l"(d) : "l"(a), "l"(b), "l"(c)); return d;
}
__device__ __forceinline__ ull mul2(ull a, ull b) {
    ull d; asm("mul.rn.f32x2 %0,%1,%2;" : "=l"(d) : "l"(a), "l"(b)); return d;
}

// Scratch (allocation-free per harness rules)
__device__ float g_hn[B * C * S];          // groupnorm output, [b][c][s]
__device__ float g_q [B * NH * HD * S];    // [b][n][d][s], pre-scaled by 1/8
__device__ float g_k [B * NH * HD * S];
__device__ float g_v [B * NH * HD * S];
__device__ float g_ao[B * C * S];          // attention out, [b][c][s] with c = d*4+n

// ---------------------------------------------------------------------------
// GroupNorm: one CTA per (b, group). 8 ch x 4096 = 32768 elems.
// ---------------------------------------------------------------------------
__global__ __launch_bounds__(256) void gn_kernel(
    const float* __restrict__ x,
    const float* __restrict__ gamma,
    const float* __restrict__ beta)
{
    int g = blockIdx.x & (NG - 1);
    int b = blockIdx.x >> 5;
    const float4* xp = (const float4*)(x + (b * C + g * GC) * S);
    float4*       hp = (float4*)(g_hn + (b * C + g * GC) * S);

    float sum = 0.f, sq = 0.f;
    for (int i = threadIdx.x; i < 8192; i += 256) {
        float4 v = xp[i];
        sum += v.x + v.y + v.z + v.w;
        sq  += v.x * v.x + v.y * v.y + v.z * v.z + v.w * v.w;
    }
    for (int o = 16; o > 0; o >>= 1) {
        sum += __shfl_xor_sync(0xffffffffu, sum, o);
        sq  += __shfl_xor_sync(0xffffffffu, sq,  o);
    }
    __shared__ float ssum[8], ssq[8], sstat[2];
    int wid = threadIdx.x >> 5, lid = threadIdx.x & 31;
    if (lid == 0) { ssum[wid] = sum; ssq[wid] = sq; }
    __syncthreads();
    if (threadIdx.x == 0) {
        float ts = 0.f, tq = 0.f;
        #pragma unroll
        for (int i = 0; i < 8; i++) { ts += ssum[i]; tq += ssq[i]; }
        float mu  = ts * (1.f / 32768.f);
        float var = tq * (1.f / 32768.f) - mu * mu;
        sstat[0] = mu;
        sstat[1] = rsqrtf(var + 1e-5f);
    }
    __syncthreads();
    float mu = sstat[0], rstd = sstat[1];

    for (int i = threadIdx.x; i < 8192; i += 256) {
        float4 v = xp[i];
        int ch = g * GC + (i >> 10);
        float gm = gamma[ch] * rstd;
        float bt = beta[ch] - mu * gm;
        float4 o;
        o.x = v.x * gm + bt; o.y = v.y * gm + bt;
        o.z = v.z * gm + bt; o.w = v.w * gm + bt;
        hp[i] = o;
    }
}

// ---------------------------------------------------------------------------
// Shared GEMM body: 64x64 tile, K=256, 128 threads, 8x4 microtile.
// Accumulators packed as f32x2 row-pairs: acc.a[rp][c] holds rows (2rp,2rp+1).
// ---------------------------------------------------------------------------
struct GemmAcc2 { ull a[4][4]; };

__device__ __forceinline__ void gemm_64x64_k256(
    const float* __restrict__ W,    // [64 rows starting m0][256], row stride 256
    const float* __restrict__ in,   // [256][4096], cols n0..n0+63
    int m0, int n0, GemmAcc2& acc)
{
    __shared__ float As[16][64];
    __shared__ float Bs[16][64];
    int tid = threadIdx.x;
    int tm = (tid >> 4) * 8, tn = (tid & 15) * 4;

    #pragma unroll
    for (int r = 0; r < 4; r++)
        #pragma unroll
        for (int c = 0; c < 4; c++) acc.a[r][c] = 0ull;

    for (int k0 = 0; k0 < 256; k0 += 16) {
        #pragma unroll
        for (int i = 0; i < 2; i++) {
            int f = tid + i * 128;          // 0..255
            int r = f >> 2;                 // 0..63
            int kc = (f & 3) * 4;           // 0,4,8,12
            float4 a = *(const float4*)&W[(m0 + r) * C + k0 + kc];
            As[kc + 0][r] = a.x; As[kc + 1][r] = a.y;
            As[kc + 2][r] = a.z; As[kc + 3][r] = a.w;
        }
        #pragma unroll
        for (int i = 0; i < 2; i++) {
            int f = tid + i * 128;
            int kr = f >> 4;                // 0..15
            int nc = (f & 15) * 4;
            *(float4*)&Bs[kr][nc] = *(const float4*)&in[(k0 + kr) * S + n0 + nc];
        }
        __syncthreads();
        #pragma unroll
        for (int k = 0; k < 16; k++) {
            ulonglong2 a01 = *(const ulonglong2*)&As[k][tm];      // pairs (0,1),(2,3)
            ulonglong2 a23 = *(const ulonglong2*)&As[k][tm + 4];  // pairs (4,5),(6,7)
            float4 bb = *(const float4*)&Bs[k][tn];
            ull b0 = pk2(bb.x, bb.x), b1 = pk2(bb.y, bb.y);
            ull b2 = pk2(bb.z, bb.z), b3 = pk2(bb.w, bb.w);
            acc.a[0][0] = fma2(a01.x, b0, acc.a[0][0]);
            acc.a[0][1] = fma2(a01.x, b1, acc.a[0][1]);
            acc.a[0][2] = fma2(a01.x, b2, acc.a[0][2]);
            acc.a[0][3] = fma2(a01.x, b3, acc.a[0][3]);
            acc.a[1][0] = fma2(a01.y, b0, acc.a[1][0]);
            acc.a[1][1] = fma2(a01.y, b1, acc.a[1][1]);
            acc.a[1][2] = fma2(a01.y, b2, acc.a[1][2]);
            acc.a[1][3] = fma2(a01.y, b3, acc.a[1][3]);
            acc.a[2][0] = fma2(a23.x, b0, acc.a[2][0]);
            acc.a[2][1] = fma2(a23.x, b1, acc.a[2][1]);
            acc.a[2][2] = fma2(a23.x, b2, acc.a[2][2]);
            acc.a[2][3] = fma2(a23.x, b3, acc.a[2][3]);
            acc.a[3][0] = fma2(a23.y, b0, acc.a[3][0]);
            acc.a[3][1] = fma2(a23.y, b1, acc.a[3][1]);
            acc.a[3][2] = fma2(a23.y, b2, acc.a[3][2]);
            acc.a[3][3] = fma2(a23.y, b3, acc.a[3][3]);
        }
        __syncthreads();
    }
}

__device__ __forceinline__ void gemm_unpack(const GemmAcc2& acc, float r8[8][4])
{
    #pragma unroll
    for (int rp = 0; rp < 4; rp++)
        #pragma unroll
        for (int c = 0; c < 4; c++)
            upk2(acc.a[rp][c], r8[2 * rp][c], r8[2 * rp + 1][c]);
}

// QKV: grid (64, 4, 6) : z = b*3 + which. Writes head-separated layout.
__global__ __launch_bounds__(128) void qkv_gemm(
    const float* __restrict__ wq, const float* __restrict__ bq,
    const float* __restrict__ wk, const float* __restrict__ bk,
    const float* __restrict__ wv, const float* __restrict__ bv)
{
    int n0 = blockIdx.x * 64;
    int m0 = blockIdx.y * 64;
    int z = blockIdx.z;
    int b = z / 3, t = z - b * 3;
    const float* W    = (t == 0) ? wq : (t == 1) ? wk : wv;
    const float* bias = (t == 0) ? bq : (t == 1) ? bk : bv;
    float* outb       = (t == 0) ? g_q : (t == 1) ? g_k : g_v;
    const float* in   = g_hn + b * C * S;
    float scale = (t == 0) ? 0.125f : 1.0f;   // q pre-scaled by d^-0.5

    GemmAcc2 acc;
    gemm_64x64_k256(W, in, m0, n0, acc);
    float r8[8][4];
    gemm_unpack(acc, r8);

    int tid = threadIdx.x;
    int tm = (tid >> 4) * 8, tn = (tid & 15) * 4;
    #pragma unroll
    for (int r = 0; r < 8; r++) {
        int o = m0 + tm + r;                 // out channel
        float bb = bias[o];
        int head = o & 3, ci = o >> 2;       // ch = ci*4 + head (head_dim leading reshape)
        float4 v;
        v.x = (r8[r][0] + bb) * scale;
        v.y = (r8[r][1] + bb) * scale;
        v.z = (r8[r][2] + bb) * scale;
        v.w = (r8[r][3] + bb) * scale;
        *(float4*)&outb[((b * NH + head) * HD + ci) * S + n0 + tn] = v;
    }
}

// Proj + residual: grid (64, 4, 2)
__global__ __launch_bounds__(128) void proj_gemm(
    const float* __restrict__ wp, const float* __restrict__ bp,
    const float* __restrict__ x, float* __restrict__ out)
{
    int n0 = blockIdx.x * 64;
    int m0 = blockIdx.y * 64;
    int b = blockIdx.z;
    const float* in = g_ao + b * C * S;

    GemmAcc2 acc;
    gemm_64x64_k256(wp, in, m0, n0, acc);
    float r8[8][4];
    gemm_unpack(acc, r8);

    int tid = threadIdx.x;
    int tm = (tid >> 4) * 8, tn = (tid & 15) * 4;
    #pragma unroll
    for (int r = 0; r < 8; r++) {
        int o = m0 + tm + r;
        float bb = bp[o];
        const float4 xr = *(const float4*)&x[(b * C + o) * S + n0 + tn];
        float4 v;
        v.x = r8[r][0] + bb + xr.x;
        v.y = r8[r][1] + bb + xr.y;
        v.z = r8[r][2] + bb + xr.z;
        v.w = r8[r][3] + bb + xr.w;
        *(float4*)&out[(b * C + o) * S + n0 + tn] = v;
    }
}

// ---------------------------------------------------------------------------
// Flash attention, f32x2 version: 1 query per thread, 128 queries per CTA.
// Scores for adjacent keys live packed in s2[8]; acc2[d] holds (even-key,
// odd-key) partial sums that are merged once at the end. All smem reads are
// warp-broadcast 128-bit loads. grid (32, 4, 2)
// ---------------------------------------------------------------------------
__global__ __launch_bounds__(128) void attn_kernel()
{
    int n = blockIdx.y, b = blockIdx.z;
    int qi = blockIdx.x * 128 + threadIdx.x;
    const float* Q = g_q + (b * NH + n) * HD * S;
    const float* K = g_k + (b * NH + n) * HD * S;
    const float* V = g_v + (b * NH + n) * HD * S;

    __shared__ float Ks[HD][64];
    __shared__ float Vs[HD][64];

    float qv[HD];
    #pragma unroll
    for (int d = 0; d < HD; d++) qv[d] = Q[d * S + qi];

    ull acc2[HD];
    #pragma unroll
    for (int d = 0; d < HD; d++) acc2[d] = 0ull;
    float m = -1e30f, l = 0.f;

    #pragma unroll 1
    for (int k0 = 0; k0 < S; k0 += 64) {
        #pragma unroll
        for (int i = 0; i < 8; i++) {
            int f = threadIdx.x + i * 128;   // 0..1023
            int d = f >> 4, j4 = (f & 15) * 4;
            *(float4*)&Ks[d][j4] = *(const float4*)&K[d * S + k0 + j4];
            *(float4*)&Vs[d][j4] = *(const float4*)&V[d * S + k0 + j4];
        }
        __syncthreads();

        #pragma unroll 1
        for (int sub = 0; sub < 4; sub++) {
            int j0 = sub * 16;
            ull s2[8];
            #pragma unroll
            for (int p = 0; p < 8; p++) s2[p] = 0ull;

            // --- QK^T: 16 keys, packed in pairs ---
            #pragma unroll
            for (int d = 0; d < HD; d++) {
                ull qdd = pk2(qv[d], qv[d]);
                ulonglong2 ka = *(const ulonglong2*)&Ks[d][j0];
                ulonglong2 kb = *(const ulonglong2*)&Ks[d][j0 + 4];
                ulonglong2 kc = *(const ulonglong2*)&Ks[d][j0 + 8];
                ulonglong2 kd = *(const ulonglong2*)&Ks[d][j0 + 12];
                s2[0] = fma2(qdd, ka.x, s2[0]);
                s2[1] = fma2(qdd, ka.y, s2[1]);
                s2[2] = fma2(qdd, kb.x, s2[2]);
                s2[3] = fma2(qdd, kb.y, s2[3]);
                s2[4] = fma2(qdd, kc.x, s2[4]);
                s2[5] = fma2(qdd, kc.y, s2[5]);
                s2[6] = fma2(qdd, kd.x, s2[6]);
                s2[7] = fma2(qdd, kd.y, s2[7]);
            }

            // --- online softmax over 16 keys ---
            float s[16];
            #pragma unroll
            for (int p = 0; p < 8; p++) upk2(s2[p], s[2 * p], s[2 * p + 1]);
            float mt = s[0];
            #pragma unroll
            for (int j = 1; j < 16; j++) mt = fmaxf(mt, s[j]);
            float mnew = fmaxf(m, mt);
            float corr = __expf(m - mnew);
            float psum = 0.f;
            #pragma unroll
            for (int j = 0; j < 16; j++) { s[j] = __expf(s[j] - mnew); psum += s[j]; }
            l = l * corr + psum;
            m = mnew;
            #pragma unroll
            for (int p = 0; p < 8; p++) s2[p] = pk2(s[2 * p], s[2 * p + 1]);

            // --- P@V: acc2[d] keeps (even-key, odd-key) lanes ---
            ull corr2 = pk2(corr, corr);
            #pragma unroll
            for (int d = 0; d < HD; d++) {
                ulonglong2 va = *(const ulonglong2*)&Vs[d][j0];
                ulonglong2 vb = *(const ulonglong2*)&Vs[d][j0 + 4];
                ulonglong2 vc = *(const ulonglong2*)&Vs[d][j0 + 8];
                ulonglong2 vd = *(const ulonglong2*)&Vs[d][j0 + 12];
                ull a = mul2(acc2[d], corr2);
                a = fma2(s2[0], va.x, a);
                a = fma2(s2[1], va.y, a);
                a = fma2(s2[2], vb.x, a);
                a = fma2(s2[3], vb.y, a);
                a = fma2(s2[4], vc.x, a);
                a = fma2(s2[5], vc.y, a);
                a = fma2(s2[6], vd.x, a);
                a = fma2(s2[7], vd.y, a);
                acc2[d] = a;
            }
        }
        __syncthreads();
    }

    float inv = 1.f / l;
    #pragma unroll
    for (int d = 0; d < HD; d++) {
        float lo, hi;
        upk2(acc2[d], lo, hi);
        g_ao[(b * C + d * NH + n) * S + qi] = (lo + hi) * inv;
    }
}

// ---------------------------------------------------------------------------
extern "C" void kernel_launch(void* const* d_in, const int* in_sizes, int n_in,
                              void* d_out, int out_size)
{
    const float* x     = (const float*)d_in[0];
    const float* gamma = (const float*)d_in[1];
    const float* beta  = (const float*)d_in[2];
    const float* wq    = (const float*)d_in[3];
    const float* bq    = (const float*)d_in[4];
    const float* wk    = (const float*)d_in[5];
    const float* bk    = (const float*)d_in[6];
    const float* wv    = (const float*)d_in[7];
    const float* bv    = (const float*)d_in[8];
    const float* wp    = (const float*)d_in[9];
    const float* bp    = (const float*)d_in[10];
    float* out = (float*)d_out;

    gn_kernel<<<B * NG, 256>>>(x, gamma, beta);
    qkv_gemm<<<dim3(S / 64, C / 64, B * 3), 128>>>(wq, bq, wk, bk, wv, bv);
    attn_kernel<<<dim3(S / 128, NH, B), 128>>>();
    proj_gemm<<<dim3(S / 64, C / 64, B), 128>>>(wp, bp, x, out);
}

// round 11
// speedup vs baseline: 6.6061x; 4.1081x over previous
#include <cuda_runtime.h>
#include <cuda_fp16.h>
#include <cuda_bf16.h>
#include <cstdint>

// Problem constants
#define B   2
#define C   256
#define S   4096      // H*W = 64*64
#define NH  4
#define HD  64        // head dim
#define NG  32
#define GC  8         // channels per group

typedef unsigned long long ull;

// ---- packed f32x2 helpers --------------------------------------------------
__device__ __forceinline__ ull pk2(float lo, float hi) {
    ull r; asm("mov.b64 %0,{%1,%2};" : "=l"(r) : "f"(lo), "f"(hi)); return r;
}
__device__ __forceinline__ void upk2(ull v, float& lo, float& hi) {
    asm("mov.b64 {%0,%1},%2;" : "=f"(lo), "=f"(hi) : "l"(v));
}
__device__ __forceinline__ ull fma2(ull a, ull b, ull c) {
    ull d; asm("fma.rn.f32x2 %0,%1,%2,%3;" : "=l"(d) : "l"(a), "l"(b), "l"(c)); return d;
}

// ---- warp-level tensor core ops (plain sm_80-era, no 'a' feature gate) -----
__device__ __forceinline__ uint32_t s2u(const void* p) {
    uint32_t a;
    asm("{ .reg .u64 t; cvta.to.shared.u64 t, %1; cvt.u32.u64 %0, t; }"
        : "=r"(a) : "l"(p));
    return a;
}

#define LDSM_X4(r0, r1, r2, r3, addr) \
    asm volatile("ldmatrix.sync.aligned.m8n8.x4.shared.b16 {%0,%1,%2,%3}, [%4];" \
        : "=r"(r0), "=r"(r1), "=r"(r2), "=r"(r3) : "r"(addr))
#define LDSM_X4_T(r0, r1, r2, r3, addr) \
    asm volatile("ldmatrix.sync.aligned.m8n8.x4.trans.shared.b16 {%0,%1,%2,%3}, [%4];" \
        : "=r"(r0), "=r"(r1), "=r"(r2), "=r"(r3) : "r"(addr))

__device__ __forceinline__ void mma16816(float c[4], const uint32_t a[4],
                                         uint32_t b0, uint32_t b1) {
    asm volatile("mma.sync.aligned.m16n8k16.row.col.f32.f16.f16.f32 "
        "{%0,%1,%2,%3}, {%4,%5,%6,%7}, {%8,%9}, {%0,%1,%2,%3};"
        : "+f"(c[0]), "+f"(c[1]), "+f"(c[2]), "+f"(c[3])
        : "r"(a[0]), "r"(a[1]), "r"(a[2]), "r"(a[3]), "r"(b0), "r"(b1));
}

// smem tile addressing: 64 halfs (128B) per row, XOR-swizzled 16B chunks
__device__ __forceinline__ int swz(int r, int c) {
    return r * 128 + ((c ^ (r & 7)) << 4);
}

// Scratch (allocation-free per harness rules)
__device__ float  g_hn[B * C * S];                // groupnorm output, [b][c][s]
__device__ __half g_qh[(size_t)B * NH * S * HD];  // [b][n][s][d], pre-scaled 1/8
__device__ __half g_kh[(size_t)B * NH * S * HD];  // [b][n][s][d]
__device__ __half g_vh[(size_t)B * NH * S * HD];  // [b][n][s][d]
__device__ float  g_ao[B * C * S];                // attn out, [b][c][s], c = d*4+n

// ---------------------------------------------------------------------------
// GroupNorm: one CTA per (b, group). 8 ch x 4096 = 32768 elems.
// ---------------------------------------------------------------------------
__global__ __launch_bounds__(256) void gn_kernel(
    const float* __restrict__ x,
    const float* __restrict__ gamma,
    const float* __restrict__ beta)
{
    int g = blockIdx.x & (NG - 1);
    int b = blockIdx.x >> 5;
    const float4* xp = (const float4*)(x + (b * C + g * GC) * S);
    float4*       hp = (float4*)(g_hn + (b * C + g * GC) * S);

    float sum = 0.f, sq = 0.f;
    for (int i = threadIdx.x; i < 8192; i += 256) {
        float4 v = xp[i];
        sum += v.x + v.y + v.z + v.w;
        sq  += v.x * v.x + v.y * v.y + v.z * v.z + v.w * v.w;
    }
    for (int o = 16; o > 0; o >>= 1) {
        sum += __shfl_xor_sync(0xffffffffu, sum, o);
        sq  += __shfl_xor_sync(0xffffffffu, sq,  o);
    }
    __shared__ float ssum[8], ssq[8], sstat[2];
    int wid = threadIdx.x >> 5, lid = threadIdx.x & 31;
    if (lid == 0) { ssum[wid] = sum; ssq[wid] = sq; }
    __syncthreads();
    if (threadIdx.x == 0) {
        float ts = 0.f, tq = 0.f;
        #pragma unroll
        for (int i = 0; i < 8; i++) { ts += ssum[i]; tq += ssq[i]; }
        float mu  = ts * (1.f / 32768.f);
        float var = tq * (1.f / 32768.f) - mu * mu;
        sstat[0] = mu;
        sstat[1] = rsqrtf(var + 1e-5f);
    }
    __syncthreads();
    float mu = sstat[0], rstd = sstat[1];

    for (int i = threadIdx.x; i < 8192; i += 256) {
        float4 v = xp[i];
        int ch = g * GC + (i >> 10);
        float gm = gamma[ch] * rstd;
        float bt = beta[ch] - mu * gm;
        float4 o;
        o.x = v.x * gm + bt; o.y = v.y * gm + bt;
        o.z = v.z * gm + bt; o.w = v.w * gm + bt;
        hp[i] = o;
    }
}

// ---------------------------------------------------------------------------
// Shared GEMM body: 64x64 tile, K=256, 128 threads, FFMA2 row-pair packing.
// ---------------------------------------------------------------------------
struct GemmAcc2 { ull a[4][4]; };

__device__ __forceinline__ void gemm_64x64_k256(
    const float* __restrict__ W,    // [64 rows from m0][256]
    const float* __restrict__ in,   // [256][4096], cols n0..n0+63
    int m0, int n0, GemmAcc2& acc)
{
    __shared__ float As[16][64];
    __shared__ float Bs[16][64];
    int tid = threadIdx.x;
    int tm = (tid >> 4) * 8, tn = (tid & 15) * 4;

    #pragma unroll
    for (int r = 0; r < 4; r++)
        #pragma unroll
        for (int c = 0; c < 4; c++) acc.a[r][c] = 0ull;

    for (int k0 = 0; k0 < 256; k0 += 16) {
        #pragma unroll
        for (int i = 0; i < 2; i++) {
            int f = tid + i * 128;
            int r = f >> 2;
            int kc = (f & 3) * 4;
            float4 a = *(const float4*)&W[(m0 + r) * C + k0 + kc];
            As[kc + 0][r] = a.x; As[kc + 1][r] = a.y;
            As[kc + 2][r] = a.z; As[kc + 3][r] = a.w;
        }
        #pragma unroll
        for (int i = 0; i < 2; i++) {
            int f = tid + i * 128;
            int kr = f >> 4;
            int nc = (f & 15) * 4;
            *(float4*)&Bs[kr][nc] = *(const float4*)&in[(k0 + kr) * S + n0 + nc];
        }
        __syncthreads();
        #pragma unroll
        for (int k = 0; k < 16; k++) {
            ulonglong2 a01 = *(const ulonglong2*)&As[k][tm];
            ulonglong2 a23 = *(const ulonglong2*)&As[k][tm + 4];
            float4 bb = *(const float4*)&Bs[k][tn];
            ull b0 = pk2(bb.x, bb.x), b1 = pk2(bb.y, bb.y);
            ull b2 = pk2(bb.z, bb.z), b3 = pk2(bb.w, bb.w);
            acc.a[0][0] = fma2(a01.x, b0, acc.a[0][0]);
            acc.a[0][1] = fma2(a01.x, b1, acc.a[0][1]);
            acc.a[0][2] = fma2(a01.x, b2, acc.a[0][2]);
            acc.a[0][3] = fma2(a01.x, b3, acc.a[0][3]);
            acc.a[1][0] = fma2(a01.y, b0, acc.a[1][0]);
            acc.a[1][1] = fma2(a01.y, b1, acc.a[1][1]);
            acc.a[1][2] = fma2(a01.y, b2, acc.a[1][2]);
            acc.a[1][3] = fma2(a01.y, b3, acc.a[1][3]);
            acc.a[2][0] = fma2(a23.x, b0, acc.a[2][0]);
            acc.a[2][1] = fma2(a23.x, b1, acc.a[2][1]);
            acc.a[2][2] = fma2(a23.x, b2, acc.a[2][2]);
            acc.a[2][3] = fma2(a23.x, b3, acc.a[2][3]);
            acc.a[3][0] = fma2(a23.y, b0, acc.a[3][0]);
            acc.a[3][1] = fma2(a23.y, b1, acc.a[3][1]);
            acc.a[3][2] = fma2(a23.y, b2, acc.a[3][2]);
            acc.a[3][3] = fma2(a23.y, b3, acc.a[3][3]);
        }
        __syncthreads();
    }
}

__device__ __forceinline__ void gemm_unpack(const GemmAcc2& acc, float r8[8][4])
{
    #pragma unroll
    for (int rp = 0; rp < 4; rp++)
        #pragma unroll
        for (int c = 0; c < 4; c++)
            upk2(acc.a[rp][c], r8[2 * rp][c], r8[2 * rp + 1][c]);
}

// QKV: grid (64, 4, 6); writes fp16 q/k/v all as [b][n][s][d].
__global__ __launch_bounds__(128) void qkv_gemm(
    const float* __restrict__ wq, const float* __restrict__ bq,
    const float* __restrict__ wk, const float* __restrict__ bk,
    const float* __restrict__ wv, const float* __restrict__ bv)
{
    int n0 = blockIdx.x * 64;
    int m0 = blockIdx.y * 64;
    int z = blockIdx.z;
    int b = z / 3, t = z - b * 3;
    const float* W    = (t == 0) ? wq : (t == 1) ? wk : wv;
    const float* bias = (t == 0) ? bq : (t == 1) ? bk : bv;
    __half* base      = (t == 0) ? g_qh : (t == 1) ? g_kh : g_vh;
    const float* in   = g_hn + b * C * S;
    float scale = (t == 0) ? 0.125f : 1.0f;   // q pre-scaled by d^-0.5

    GemmAcc2 acc;
    gemm_64x64_k256(W, in, m0, n0, acc);
    float r8[8][4];
    gemm_unpack(acc, r8);

    int tid = threadIdx.x;
    int tm = (tid >> 4) * 8, tn = (tid & 15) * 4;
    #pragma unroll
    for (int r = 0; r < 8; r++) {
        int o = m0 + tm + r;
        float bb = bias[o];
        int head = o & 3, ci = o >> 2;       // ch = ci*4 + head
        __half* dst = base + ((size_t)(b * NH + head) * S + (n0 + tn)) * HD + ci;
        dst[0 * HD] = __float2half_rn((r8[r][0] + bb) * scale);
        dst[1 * HD] = __float2half_rn((r8[r][1] + bb) * scale);
        dst[2 * HD] = __float2half_rn((r8[r][2] + bb) * scale);
        dst[3 * HD] = __float2half_rn((r8[r][3] + bb) * scale);
    }
}

// Proj + residual: grid (64, 4, 2), fp32
__global__ __launch_bounds__(128) void proj_gemm(
    const float* __restrict__ wp, const float* __restrict__ bp,
    const float* __restrict__ x, float* __restrict__ out)
{
    int n0 = blockIdx.x * 64;
    int m0 = blockIdx.y * 64;
    int b = blockIdx.z;
    const float* in = g_ao + b * C * S;

    GemmAcc2 acc;
    gemm_64x64_k256(wp, in, m0, n0, acc);
    float r8[8][4];
    gemm_unpack(acc, r8);

    int tid = threadIdx.x;
    int tm = (tid >> 4) * 8, tn = (tid & 15) * 4;
    #pragma unroll
    for (int r = 0; r < 8; r++) {
        int o = m0 + tm + r;
        float bb = bp[o];
        const float4 xr = *(const float4*)&x[(b * C + o) * S + n0 + tn];
        float4 v;
        v.x = r8[r][0] + bb + xr.x;
        v.y = r8[r][1] + bb + xr.y;
        v.z = r8[r][2] + bb + xr.z;
        v.w = r8[r][3] + bb + xr.w;
        *(float4*)&out[(b * C + o) * S + n0 + tn] = v;
    }
}

// ---------------------------------------------------------------------------
// Flash attention via mma.sync.m16n8k16 (HMMA tensor pipe; no tcgen05 —
// harness PTX targets plain sm_103 which lacks the 'a' feature set).
// CTA = 64 queries (4 warps x 16 rows), K-tiles of 64 keys.
//   QK: A = Q-frags (ldmatrix of Q[s][d]), B = K rows (ldmatrix, [s][d] is
//       col-major k x n for row.col mma).
//   softmax on C-frags in registers; C-layout == next A-layout, so P stays
//       in registers (pack pairs to half2).
//   PV: B = V via ldmatrix.trans of V[s][d].
// grid (64, 4, 2), 128 threads, 24KB static smem.
// ---------------------------------------------------------------------------
__global__ __launch_bounds__(128) void attn_kernel()
{
    __shared__ __align__(16) char sm[24576];  // Q:0..8K, K:8K..16K, V:16K..24K
    uint32_t sQ = s2u(sm);
    uint32_t sK = sQ + 8192;
    uint32_t sV = sQ + 16384;

    int tid = threadIdx.x, w = tid >> 5, l = tid & 31;
    int n = blockIdx.y, b = blockIdx.z;
    int bn = b * NH + n;
    int q0 = blockIdx.x * 64;
    const __half* Qg = g_qh + ((size_t)bn * S + q0) * HD;
    const __half* Kg = g_kh + (size_t)bn * S * HD;
    const __half* Vg = g_vh + (size_t)bn * S * HD;

    // Load Q tile 64x64 (8KB), swizzled
    #pragma unroll
    for (int i = 0; i < 4; i++) {
        int f = tid + i * 128;               // 0..511
        int r = f >> 3, c = f & 7;
        *(uint4*)(sm + swz(r, c)) = *(const uint4*)(Qg + r * HD + c * 8);
    }
    __syncthreads();

    // Q A-fragments: 4 k-steps of m16k16
    uint32_t qa[4][4];
    #pragma unroll
    for (int t = 0; t < 4; t++) {
        int qr = 16 * w + (l & 15);
        int c = 2 * t + (l >> 4);
        LDSM_X4(qa[t][0], qa[t][1], qa[t][2], qa[t][3], sQ + swz(qr, c));
    }

    float o[8][4];
    #pragma unroll
    for (int j = 0; j < 8; j++)
        #pragma unroll
        for (int e = 0; e < 4; e++) o[j][e] = 0.f;
    float m0 = -1e30f, m1 = -1e30f, l0 = 0.f, l1 = 0.f;

    #pragma unroll 1
    for (int k0 = 0; k0 < S; k0 += 64) {
        __syncthreads();
        #pragma unroll
        for (int i = 0; i < 4; i++) {
            int f = tid + i * 128;
            int r = f >> 3, c = f & 7;
            *(uint4*)(sm + 8192  + swz(r, c)) = *(const uint4*)(Kg + (size_t)(k0 + r) * HD + c * 8);
            *(uint4*)(sm + 16384 + swz(r, c)) = *(const uint4*)(Vg + (size_t)(k0 + r) * HD + c * 8);
        }
        __syncthreads();

        // ---- S = Q K^T : 8 n-tiles (8 keys each) ----
        float s[8][4];
        #pragma unroll
        for (int j = 0; j < 8; j++)
            #pragma unroll
            for (int e = 0; e < 4; e++) s[j][e] = 0.f;

        #pragma unroll
        for (int jp = 0; jp < 4; jp++) {
            #pragma unroll
            for (int t = 0; t < 4; t++) {
                int key = 8 * (2 * jp + (l >> 4)) + (l & 7);
                int c = 2 * t + ((l >> 3) & 1);
                uint32_t b0, b1, b2, b3;
                LDSM_X4(b0, b1, b2, b3, sK + swz(key, c));
                mma16816(s[2 * jp],     qa[t], b0, b1);
                mma16816(s[2 * jp + 1], qa[t], b2, b3);
            }
        }

        // ---- online softmax: rows l/4 (elems 0,1) and l/4+8 (elems 2,3) ----
        float mt0 = -1e30f, mt1 = -1e30f;
        #pragma unroll
        for (int j = 0; j < 8; j++) {
            mt0 = fmaxf(mt0, fmaxf(s[j][0], s[j][1]));
            mt1 = fmaxf(mt1, fmaxf(s[j][2], s[j][3]));
        }
        mt0 = fmaxf(mt0, __shfl_xor_sync(0xffffffffu, mt0, 1));
        mt0 = fmaxf(mt0, __shfl_xor_sync(0xffffffffu, mt0, 2));
        mt1 = fmaxf(mt1, __shfl_xor_sync(0xffffffffu, mt1, 1));
        mt1 = fmaxf(mt1, __shfl_xor_sync(0xffffffffu, mt1, 2));
        float mn0 = fmaxf(m0, mt0), mn1 = fmaxf(m1, mt1);
        float corr0 = __expf(m0 - mn0), corr1 = __expf(m1 - mn1);
        m0 = mn0; m1 = mn1;

        float ps0 = 0.f, ps1 = 0.f;
        #pragma unroll
        for (int j = 0; j < 8; j++) {
            s[j][0] = __expf(s[j][0] - mn0);
            s[j][1] = __expf(s[j][1] - mn0);
            s[j][2] = __expf(s[j][2] - mn1);
            s[j][3] = __expf(s[j][3] - mn1);
            ps0 += s[j][0] + s[j][1];
            ps1 += s[j][2] + s[j][3];
        }
        ps0 += __shfl_xor_sync(0xffffffffu, ps0, 1);
        ps0 += __shfl_xor_sync(0xffffffffu, ps0, 2);
        ps1 += __shfl_xor_sync(0xffffffffu, ps1, 1);
        ps1 += __shfl_xor_sync(0xffffffffu, ps1, 2);
        l0 = l0 * corr0 + ps0;
        l1 = l1 * corr1 + ps1;

        // pack P fragments: C-layout of tiles (2t,2t+1) == A-layout of kstep t
        uint32_t pa[4][4];
        #pragma unroll
        for (int t = 0; t < 4; t++) {
            __half2 h0 = __floats2half2_rn(s[2 * t][0],     s[2 * t][1]);
            __half2 h1 = __floats2half2_rn(s[2 * t][2],     s[2 * t][3]);
            __half2 h2 = __floats2half2_rn(s[2 * t + 1][0], s[2 * t + 1][1]);
            __half2 h3 = __floats2half2_rn(s[2 * t + 1][2], s[2 * t + 1][3]);
            pa[t][0] = *(uint32_t*)&h0; pa[t][1] = *(uint32_t*)&h1;
            pa[t][2] = *(uint32_t*)&h2; pa[t][3] = *(uint32_t*)&h3;
        }

        // rescale O
        #pragma unroll
        for (int j = 0; j < 8; j++) {
            o[j][0] *= corr0; o[j][1] *= corr0;
            o[j][2] *= corr1; o[j][3] *= corr1;
        }

        // ---- O += P V ----
        #pragma unroll
        for (int jp = 0; jp < 4; jp++) {
            #pragma unroll
            for (int t = 0; t < 4; t++) {
                int key = 16 * t + (l & 7) + 8 * ((l >> 3) & 1);
                int c = 2 * jp + (l >> 4);
                uint32_t b0, b1, b2, b3;
                LDSM_X4_T(b0, b1, b2, b3, sV + swz(key, c));
                mma16816(o[2 * jp],     pa[t], b0, b1);
                mma16816(o[2 * jp + 1], pa[t], b2, b3);
            }
        }
    }

    // ---- epilogue: stage O [d][q] (stride 65) in smem, coalesced write ----
    float inv0 = 1.f / l0, inv1 = 1.f / l1;
    __syncthreads();
    float* oS = (float*)sm;
    int qr = 16 * w + (l >> 2);              // local q row (first of pair)
    #pragma unroll
    for (int j = 0; j < 8; j++) {
        int d = 8 * j + 2 * (l & 3);
        oS[(d + 0) * 65 + qr]     = o[j][0] * inv0;
        oS[(d + 1) * 65 + qr]     = o[j][1] * inv0;
        oS[(d + 0) * 65 + qr + 8] = o[j][2] * inv1;
        oS[(d + 1) * 65 + qr + 8] = o[j][3] * inv1;
    }
    __syncthreads();
    #pragma unroll
    for (int i = 0; i < 8; i++) {
        int f = tid + i * 128;               // 0..1023
        int d = f >> 4, q4 = (f & 15) * 4;
        float4 v;
        v.x = oS[d * 65 + q4 + 0];
        v.y = oS[d * 65 + q4 + 1];
        v.z = oS[d * 65 + q4 + 2];
        v.w = oS[d * 65 + q4 + 3];
        *(float4*)&g_ao[(b * C + d * NH + n) * S + q0 + q4] = v;
    }
}

// ---------------------------------------------------------------------------
extern "C" void kernel_launch(void* const* d_in, const int* in_sizes, int n_in,
                              void* d_out, int out_size)
{
    const float* x     = (const float*)d_in[0];
    const float* gamma = (const float*)d_in[1];
    const float* beta  = (const float*)d_in[2];
    const float* wq    = (const float*)d_in[3];
    const float* bq    = (const float*)d_in[4];
    const float* wk    = (const float*)d_in[5];
    const float* bk    = (const float*)d_in[6];
    const float* wv    = (const float*)d_in[7];
    const float* bv    = (const float*)d_in[8];
    const float* wp    = (const float*)d_in[9];
    const float* bp    = (const float*)d_in[10];
    float* out = (float*)d_out;

    gn_kernel<<<B * NG, 256>>>(x, gamma, beta);
    qkv_gemm<<<dim3(S / 64, C / 64, B * 3), 128>>>(wq, bq, wk, bk, wv, bv);
    attn_kernel<<<dim3(S / 64, NH, B), 128>>>();
    proj_gemm<<<dim3(S / 64, C / 64, B), 128>>>(wp, bp, x, out);
}

// round 16
// speedup vs baseline: 9.3561x; 1.4163x over previous
#include <cuda_runtime.h>
#include <cuda_fp16.h>
#include <cuda_bf16.h>
#include <cstdint>

// Problem constants
#define B   2
#define C   256
#define S   4096      // H*W = 64*64
#define NH  4
#define HD  64        // head dim
#define NG  32
#define GC  8         // channels per group

// ---- warp-level tensor core ops (plain sm_80-era, no 'a' feature gate) -----
__device__ __forceinline__ uint32_t s2u(const void* p) {
    uint32_t a;
    asm("{ .reg .u64 t; cvta.to.shared.u64 t, %1; cvt.u32.u64 %0, t; }"
        : "=r"(a) : "l"(p));
    return a;
}

#define LDSM_X4(r0, r1, r2, r3, addr) \
    asm volatile("ldmatrix.sync.aligned.m8n8.x4.shared.b16 {%0,%1,%2,%3}, [%4];" \
        : "=r"(r0), "=r"(r1), "=r"(r2), "=r"(r3) : "r"(addr))
#define LDSM_X4_T(r0, r1, r2, r3, addr) \
    asm volatile("ldmatrix.sync.aligned.m8n8.x4.trans.shared.b16 {%0,%1,%2,%3}, [%4];" \
        : "=r"(r0), "=r"(r1), "=r"(r2), "=r"(r3) : "r"(addr))

__device__ __forceinline__ void mma16816(float c[4], const uint32_t a[4],
                                         uint32_t b0, uint32_t b1) {
    asm volatile("mma.sync.aligned.m16n8k16.row.col.f32.f16.f16.f32 "
        "{%0,%1,%2,%3}, {%4,%5,%6,%7}, {%8,%9}, {%0,%1,%2,%3};"
        : "+f"(c[0]), "+f"(c[1]), "+f"(c[2]), "+f"(c[3])
        : "r"(a[0]), "r"(a[1]), "r"(a[2]), "r"(a[3]), "r"(b0), "r"(b1));
}

// smem tile addressing: 64 halfs (128B) per row, XOR-swizzled 16B chunks
__device__ __forceinline__ int swz(int r, int c) {
    return r * 128 + ((c ^ (r & 7)) << 4);
}

// Scratch (allocation-free per harness rules)
__device__ __half g_hnh[(size_t)B * C * S];       // groupnorm out fp16, [b][c][s]
__device__ __half g_wh[4][C * C];                 // fp16 weights: q,k,v,p
__device__ __half g_qh[(size_t)B * NH * S * HD];  // [b][n][s][d], pre-scaled 1/8
__device__ __half g_kh[(size_t)B * NH * S * HD];  // [b][n][s][d]
__device__ __half g_vh[(size_t)B * NH * S * HD];  // [b][n][s][d]
__device__ __half g_aoh[(size_t)B * C * S];       // attn out fp16, [b][c][s], c=d*4+n

// ---------------------------------------------------------------------------
// Weight prep: fp32 -> fp16 for all four 256x256 weight matrices.
// grid 64 x 256 threads: 16384 threads, one float4 per matrix each.
// ---------------------------------------------------------------------------
__global__ __launch_bounds__(256) void wprep_kernel(
    const float* __restrict__ wq, const float* __restrict__ wk,
    const float* __restrict__ wv, const float* __restrict__ wp)
{
    int i = blockIdx.x * 256 + threadIdx.x;      // 0..16383, float4 index
    const float4* src[4] = {(const float4*)wq, (const float4*)wk,
                            (const float4*)wv, (const float4*)wp};
    #pragma unroll
    for (int t = 0; t < 4; t++) {
        float4 v = src[t][i];
        __half2 h0 = __floats2half2_rn(v.x, v.y);
        __half2 h1 = __floats2half2_rn(v.z, v.w);
        uint2 u;
        u.x = *(uint32_t*)&h0; u.y = *(uint32_t*)&h1;
        *(uint2*)&g_wh[t][i * 4] = u;
    }
}

// ---------------------------------------------------------------------------
// GroupNorm: one CTA per (b, group). 8 ch x 4096 = 32768 elems. fp16 out.
// ---------------------------------------------------------------------------
__global__ __launch_bounds__(256) void gn_kernel(
    const float* __restrict__ x,
    const float* __restrict__ gamma,
    const float* __restrict__ beta)
{
    int g = blockIdx.x & (NG - 1);
    int b = blockIdx.x >> 5;
    const float4* xp = (const float4*)(x + (b * C + g * GC) * S);
    __half* hp = g_hnh + (size_t)(b * C + g * GC) * S;

    float sum = 0.f, sq = 0.f;
    for (int i = threadIdx.x; i < 8192; i += 256) {
        float4 v = xp[i];
        sum += v.x + v.y + v.z + v.w;
        sq  += v.x * v.x + v.y * v.y + v.z * v.z + v.w * v.w;
    }
    for (int o = 16; o > 0; o >>= 1) {
        sum += __shfl_xor_sync(0xffffffffu, sum, o);
        sq  += __shfl_xor_sync(0xffffffffu, sq,  o);
    }
    __shared__ float ssum[8], ssq[8], sstat[2];
    int wid = threadIdx.x >> 5, lid = threadIdx.x & 31;
    if (lid == 0) { ssum[wid] = sum; ssq[wid] = sq; }
    __syncthreads();
    if (threadIdx.x == 0) {
        float ts = 0.f, tq = 0.f;
        #pragma unroll
        for (int i = 0; i < 8; i++) { ts += ssum[i]; tq += ssq[i]; }
        float mu  = ts * (1.f / 32768.f);
        float var = tq * (1.f / 32768.f) - mu * mu;
        sstat[0] = mu;
        sstat[1] = rsqrtf(var + 1e-5f);
    }
    __syncthreads();
    float mu = sstat[0], rstd = sstat[1];

    for (int i = threadIdx.x; i < 8192; i += 256) {
        float4 v = xp[i];
        int ch = g * GC + (i >> 10);
        float gm = gamma[ch] * rstd;
        float bt = beta[ch] - mu * gm;
        __half2 h0 = __floats2half2_rn(v.x * gm + bt, v.y * gm + bt);
        __half2 h1 = __floats2half2_rn(v.z * gm + bt, v.w * gm + bt);
        uint2 u;
        u.x = *(uint32_t*)&h0; u.y = *(uint32_t*)&h1;
        *(uint2*)&hp[i * 4] = u;
    }
}

// ---------------------------------------------------------------------------
// HMMA GEMM body: out-tile 64(ch) x 64(px), K=256 in four 64-chunks.
// A = W fp16 [m][k] row-major (ldmatrix), B = src fp16 [k][n] (ldmatrix.trans).
// 4 warps, warp = m16 strip x n64; acc[8 n-tiles][4].
// ---------------------------------------------------------------------------
__device__ __forceinline__ void hmma_gemm(
    char* smA, char* smB,
    const __half* __restrict__ A, const __half* __restrict__ Bsrc,
    int m0, int n0, float acc[8][4])
{
    uint32_t sA = s2u(smA), sB = s2u(smB);
    int tid = threadIdx.x, w = tid >> 5, l = tid & 31;

    #pragma unroll
    for (int j = 0; j < 8; j++)
        #pragma unroll
        for (int e = 0; e < 4; e++) acc[j][e] = 0.f;

    #pragma unroll 1
    for (int k0 = 0; k0 < C; k0 += 64) {
        #pragma unroll
        for (int i = 0; i < 4; i++) {
            int f = tid + i * 128;               // 0..511
            int r = f >> 3, c = f & 7;
            *(uint4*)(smA + swz(r, c)) = *(const uint4*)(A + (size_t)(m0 + r) * C + k0 + c * 8);
            *(uint4*)(smB + swz(r, c)) = *(const uint4*)(Bsrc + (size_t)(k0 + r) * S + n0 + c * 8);
        }
        __syncthreads();

        uint32_t af[4][4];
        #pragma unroll
        for (int t = 0; t < 4; t++) {
            int r = 16 * w + (l & 15);
            int c = 2 * t + (l >> 4);
            LDSM_X4(af[t][0], af[t][1], af[t][2], af[t][3], sA + swz(r, c));
        }
        #pragma unroll
        for (int jp = 0; jp < 4; jp++) {
            #pragma unroll
            for (int t = 0; t < 4; t++) {
                int kr = 16 * t + (l & 7) + 8 * ((l >> 3) & 1);
                int c = 2 * jp + (l >> 4);
                uint32_t b0, b1, b2, b3;
                LDSM_X4_T(b0, b1, b2, b3, sB + swz(kr, c));
                mma16816(acc[2 * jp],     af[t], b0, b1);
                mma16816(acc[2 * jp + 1], af[t], b2, b3);
            }
        }
        __syncthreads();
    }
}

// QKV: grid (64, 4, 6), z = b*3 + t; writes fp16 q/k/v as [b][n][s][d].
__global__ __launch_bounds__(128) void qkv_gemm(
    const float* __restrict__ bq, const float* __restrict__ bk,
    const float* __restrict__ bv)
{
    __shared__ __align__(16) char smA[8192], smB[8192];
    int n0 = blockIdx.x * 64;
    int m0 = blockIdx.y * 64;
    int z = blockIdx.z;
    int b = z / 3, t = z - b * 3;
    const float* bias = (t == 0) ? bq : (t == 1) ? bk : bv;
    __half* base      = (t == 0) ? g_qh : (t == 1) ? g_kh : g_vh;
    float scale = (t == 0) ? 0.125f : 1.0f;      // q pre-scaled by d^-0.5

    float acc[8][4];
    hmma_gemm(smA, smB, g_wh[t], g_hnh + (size_t)b * C * S, m0, n0, acc);

    int l = threadIdx.x & 31, w = threadIdx.x >> 5;
    int r0 = m0 + 16 * w + (l >> 2);             // out channel (row), and r0+8
    float bb0 = bias[r0], bb1 = bias[r0 + 8];
    int h0 = r0 & 3, c0 = r0 >> 2;
    int h1 = (r0 + 8) & 3, c1 = (r0 + 8) >> 2;
    __half* d0 = base + (size_t)(b * NH + h0) * S * HD + c0;
    __half* d1 = base + (size_t)(b * NH + h1) * S * HD + c1;
    #pragma unroll
    for (int j = 0; j < 8; j++) {
        int px = n0 + 8 * j + 2 * (l & 3);
        d0[(size_t)(px)     * HD] = __float2half_rn((acc[j][0] + bb0) * scale);
        d0[(size_t)(px + 1) * HD] = __float2half_rn((acc[j][1] + bb0) * scale);
        d1[(size_t)(px)     * HD] = __float2half_rn((acc[j][2] + bb1) * scale);
        d1[(size_t)(px + 1) * HD] = __float2half_rn((acc[j][3] + bb1) * scale);
    }
}

// Proj + bias + residual: grid (64, 4, 2), fp32 output.
__global__ __launch_bounds__(128) void proj_gemm(
    const float* __restrict__ bp,
    const float* __restrict__ x, float* __restrict__ out)
{
    __shared__ __align__(16) char smA[8192], smB[8192];
    int n0 = blockIdx.x * 64;
    int m0 = blockIdx.y * 64;
    int b = blockIdx.z;

    float acc[8][4];
    hmma_gemm(smA, smB, g_wh[3], g_aoh + (size_t)b * C * S, m0, n0, acc);

    int l = threadIdx.x & 31, w = threadIdx.x >> 5;
    int r0 = m0 + 16 * w + (l >> 2);
    float bb0 = bp[r0], bb1 = bp[r0 + 8];
    const float* x0 = x + (size_t)(b * C + r0) * S;
    const float* x1 = x0 + 8 * S;
    float* o0 = out + (size_t)(b * C + r0) * S;
    float* o1 = o0 + 8 * S;
    #pragma unroll
    for (int j = 0; j < 8; j++) {
        int px = n0 + 8 * j + 2 * (l & 3);
        float2 xa = *(const float2*)&x0[px];
        float2 xb = *(const float2*)&x1[px];
        float2 va, vb;
        va.x = acc[j][0] + bb0 + xa.x;
        va.y = acc[j][1] + bb0 + xa.y;
        vb.x = acc[j][2] + bb1 + xb.x;
        vb.y = acc[j][3] + bb1 + xb.y;
        *(float2*)&o0[px] = va;
        *(float2*)&o1[px] = vb;
    }
}

// ---------------------------------------------------------------------------
// Flash attention via mma.sync.m16n8k16 (HMMA tensor pipe).
// CTA = 64 queries (4 warps x 16 rows), K-tiles of 64 keys.
// grid (64, 4, 2), 128 threads, 24KB static smem.
// ---------------------------------------------------------------------------
__global__ __launch_bounds__(128) void attn_kernel()
{
    __shared__ __align__(16) char sm[24576];  // Q:0..8K, K:8K..16K, V:16K..24K
    uint32_t sQ = s2u(sm);
    uint32_t sK = sQ + 8192;
    uint32_t sV = sQ + 16384;

    int tid = threadIdx.x, w = tid >> 5, l = tid & 31;
    int n = blockIdx.y, b = blockIdx.z;
    int bn = b * NH + n;
    int q0 = blockIdx.x * 64;
    const __half* Qg = g_qh + ((size_t)bn * S + q0) * HD;
    const __half* Kg = g_kh + (size_t)bn * S * HD;
    const __half* Vg = g_vh + (size_t)bn * S * HD;

    // Load Q tile 64x64 (8KB), swizzled
    #pragma unroll
    for (int i = 0; i < 4; i++) {
        int f = tid + i * 128;               // 0..511
        int r = f >> 3, c = f & 7;
        *(uint4*)(sm + swz(r, c)) = *(const uint4*)(Qg + r * HD + c * 8);
    }
    __syncthreads();

    // Q A-fragments: 4 k-steps of m16k16
    uint32_t qa[4][4];
    #pragma unroll
    for (int t = 0; t < 4; t++) {
        int qr = 16 * w + (l & 15);
        int c = 2 * t + (l >> 4);
        LDSM_X4(qa[t][0], qa[t][1], qa[t][2], qa[t][3], sQ + swz(qr, c));
    }

    float o[8][4];
    #pragma unroll
    for (int j = 0; j < 8; j++)
        #pragma unroll
        for (int e = 0; e < 4; e++) o[j][e] = 0.f;
    float m0 = -1e30f, m1 = -1e30f, l0 = 0.f, l1 = 0.f;

    #pragma unroll 1
    for (int k0 = 0; k0 < S; k0 += 64) {
        __syncthreads();
        #pragma unroll
        for (int i = 0; i < 4; i++) {
            int f = tid + i * 128;
            int r = f >> 3, c = f & 7;
            *(uint4*)(sm + 8192  + swz(r, c)) = *(const uint4*)(Kg + (size_t)(k0 + r) * HD + c * 8);
            *(uint4*)(sm + 16384 + swz(r, c)) = *(const uint4*)(Vg + (size_t)(k0 + r) * HD + c * 8);
        }
        __syncthreads();

        // ---- S = Q K^T : 8 n-tiles (8 keys each) ----
        float s[8][4];
        #pragma unroll
        for (int j = 0; j < 8; j++)
            #pragma unroll
            for (int e = 0; e < 4; e++) s[j][e] = 0.f;

        #pragma unroll
        for (int jp = 0; jp < 4; jp++) {
            #pragma unroll
            for (int t = 0; t < 4; t++) {
                int key = 8 * (2 * jp + (l >> 4)) + (l & 7);
                int c = 2 * t + ((l >> 3) & 1);
                uint32_t b0, b1, b2, b3;
                LDSM_X4(b0, b1, b2, b3, sK + swz(key, c));
                mma16816(s[2 * jp],     qa[t], b0, b1);
                mma16816(s[2 * jp + 1], qa[t], b2, b3);
            }
        }

        // ---- online softmax ----
        float mt0 = -1e30f, mt1 = -1e30f;
        #pragma unroll
        for (int j = 0; j < 8; j++) {
            mt0 = fmaxf(mt0, fmaxf(s[j][0], s[j][1]));
            mt1 = fmaxf(mt1, fmaxf(s[j][2], s[j][3]));
        }
        mt0 = fmaxf(mt0, __shfl_xor_sync(0xffffffffu, mt0, 1));
        mt0 = fmaxf(mt0, __shfl_xor_sync(0xffffffffu, mt0, 2));
        mt1 = fmaxf(mt1, __shfl_xor_sync(0xffffffffu, mt1, 1));
        mt1 = fmaxf(mt1, __shfl_xor_sync(0xffffffffu, mt1, 2));
        float mn0 = fmaxf(m0, mt0), mn1 = fmaxf(m1, mt1);
        float corr0 = __expf(m0 - mn0), corr1 = __expf(m1 - mn1);
        m0 = mn0; m1 = mn1;

        float ps0 = 0.f, ps1 = 0.f;
        #pragma unroll
        for (int j = 0; j < 8; j++) {
            s[j][0] = __expf(s[j][0] - mn0);
            s[j][1] = __expf(s[j][1] - mn0);
            s[j][2] = __expf(s[j][2] - mn1);
            s[j][3] = __expf(s[j][3] - mn1);
            ps0 += s[j][0] + s[j][1];
            ps1 += s[j][2] + s[j][3];
        }
        ps0 += __shfl_xor_sync(0xffffffffu, ps0, 1);
        ps0 += __shfl_xor_sync(0xffffffffu, ps0, 2);
        ps1 += __shfl_xor_sync(0xffffffffu, ps1, 1);
        ps1 += __shfl_xor_sync(0xffffffffu, ps1, 2);
        l0 = l0 * corr0 + ps0;
        l1 = l1 * corr1 + ps1;

        // pack P fragments: C-layout of tiles (2t,2t+1) == A-layout of kstep t
        uint32_t pa[4][4];
        #pragma unroll
        for (int t = 0; t < 4; t++) {
            __half2 h0 = __floats2half2_rn(s[2 * t][0],     s[2 * t][1]);
            __half2 h1 = __floats2half2_rn(s[2 * t][2],     s[2 * t][3]);
            __half2 h2 = __floats2half2_rn(s[2 * t + 1][0], s[2 * t + 1][1]);
            __half2 h3 = __floats2half2_rn(s[2 * t + 1][2], s[2 * t + 1][3]);
            pa[t][0] = *(uint32_t*)&h0; pa[t][1] = *(uint32_t*)&h1;
            pa[t][2] = *(uint32_t*)&h2; pa[t][3] = *(uint32_t*)&h3;
        }

        // rescale O
        #pragma unroll
        for (int j = 0; j < 8; j++) {
            o[j][0] *= corr0; o[j][1] *= corr0;
            o[j][2] *= corr1; o[j][3] *= corr1;
        }

        // ---- O += P V ----
        #pragma unroll
        for (int jp = 0; jp < 4; jp++) {
            #pragma unroll
            for (int t = 0; t < 4; t++) {
                int key = 16 * t + (l & 7) + 8 * ((l >> 3) & 1);
                int c = 2 * jp + (l >> 4);
                uint32_t b0, b1, b2, b3;
                LDSM_X4_T(b0, b1, b2, b3, sV + swz(key, c));
                mma16816(o[2 * jp],     pa[t], b0, b1);
                mma16816(o[2 * jp + 1], pa[t], b2, b3);
            }
        }
    }

    // ---- epilogue: stage O [d][q] (stride 65) in smem, coalesced fp16 write ----
    float inv0 = 1.f / l0, inv1 = 1.f / l1;
    __syncthreads();
    float* oS = (float*)sm;
    int qr = 16 * w + (l >> 2);
    #pragma unroll
    for (int j = 0; j < 8; j++) {
        int d = 8 * j + 2 * (l & 3);
        oS[(d + 0) * 65 + qr]     = o[j][0] * inv0;
        oS[(d + 1) * 65 + qr]     = o[j][1] * inv0;
        oS[(d + 0) * 65 + qr + 8] = o[j][2] * inv1;
        oS[(d + 1) * 65 + qr + 8] = o[j][3] * inv1;
    }
    __syncthreads();
    #pragma unroll
    for (int i = 0; i < 8; i++) {
        int f = tid + i * 128;               // 0..1023
        int d = f >> 4, q4 = (f & 15) * 4;
        __half2 h0 = __floats2half2_rn(oS[d * 65 + q4 + 0], oS[d * 65 + q4 + 1]);
        __half2 h1 = __floats2half2_rn(oS[d * 65 + q4 + 2], oS[d * 65 + q4 + 3]);
        uint2 u;
        u.x = *(uint32_t*)&h0; u.y = *(uint32_t*)&h1;
        *(uint2*)&g_aoh[(size_t)(b * C + d * NH + n) * S + q0 + q4] = u;
    }
}

// ---------------------------------------------------------------------------
extern "C" void kernel_launch(void* const* d_in, const int* in_sizes, int n_in,
                              void* d_out, int out_size)
{
    const float* x     = (const float*)d_in[0];
    const float* gamma = (const float*)d_in[1];
    const float* beta  = (const float*)d_in[2];
    const float* wq    = (const float*)d_in[3];
    const float* bq    = (const float*)d_in[4];
    const float* wk    = (const float*)d_in[5];
    const float* bk    = (const float*)d_in[6];
    const float* wv    = (const float*)d_in[7];
    const float* bv    = (const float*)d_in[8];
    const float* wp    = (const float*)d_in[9];
    const float* bp    = (const float*)d_in[10];
    float* out = (float*)d_out;

    wprep_kernel<<<64, 256>>>(wq, wk, wv, wp);
    gn_kernel<<<B * NG, 256>>>(x, gamma, beta);
    qkv_gemm<<<dim3(S / 64, C / 64, B * 3), 128>>>(bq, bk, bv);
    attn_kernel<<<dim3(S / 64, NH, B), 128>>>();
    proj_gemm<<<dim3(S / 64, C / 64, B), 128>>>(bp, x, out);
}